// round 1
// baseline (speedup 1.0000x reference)
#include <cuda_runtime.h>
#include <cstdint>

// Problem constants (fixed by setup_inputs)
#define BATCH   32
#define CH      2
#define HH      480
#define WW      864
#define IGNORE_L 255

#define RADIUS  7
#define TX      256
#define TY      64
#define IN_ROWS (TY + 2*RADIUS)   // 78 input rows
#define IN_WORDS 9                // 288 input cols, base = x0-16
#define NTHREADS 256
#define NWARPS   8

__device__ double g_sum;
__device__ unsigned long long g_cnt;

__global__ void bl_init_kernel() {
    g_sum = 0.0;
    g_cnt = 0ULL;
}

__global__ __launch_bounds__(NTHREADS)
void boundary_loss_kernel(const float* __restrict__ logits,
                          const int*   __restrict__ labels) {
    __shared__ uint32_t sB1[IN_ROWS][IN_WORDS];  // original label==1 bits (kept for label lookup)
    __shared__ uint32_t sM0[IN_ROWS][IN_WORDS];  // morph-0 bits; overwritten in-place by h-spread
    __shared__ uint32_t sH1[IN_ROWS][IN_WORDS];  // h-spread of sB1
    __shared__ float    sPartS[NWARPS];
    __shared__ unsigned sPartC[NWARPS];

    const int b   = blockIdx.z;
    const int x0  = blockIdx.x * TX;
    const int y0  = blockIdx.y * TY;
    const int tid  = threadIdx.x;
    const int lane = tid & 31;
    const int warp = tid >> 5;
    const int baseCol = x0 - 16;

    // ---------------- Phase 1: pack labels into bit masks -------------------
    // One warp packs one (row, word) per iteration: coalesced 32-int load + 2 ballots.
    for (int t = warp; t < IN_ROWS * IN_WORDS; t += NWARPS) {
        const int ir = t / IN_WORDS;
        const int wi = t - ir * IN_WORDS;
        const int y   = y0 - RADIUS + ir;
        const int col = baseCol + (wi << 5) + lane;
        int lbl = -1;
        if ((unsigned)y < (unsigned)HH && (unsigned)col < (unsigned)WW)
            lbl = labels[(b * HH + y) * WW + col];
        // np_label = 0 for (label==0) OR (label==IGNORE); = 255 for label==1.
        // Out-of-bounds contributes neither (erode pad=+inf, dilate pad=-inf).
        const unsigned m1 = __ballot_sync(0xffffffffu, lbl == 1);
        const unsigned m0 = __ballot_sync(0xffffffffu, lbl == 0 || lbl == IGNORE_L);
        if (lane == 0) { sB1[ir][wi] = m1; sM0[ir][wi] = m0; }
    }
    __syncthreads();

    // ---------------- Phase 2: horizontal radius-7 OR (log-doubling) --------
    // 156 independent tasks: (row, which-mask). Each loads its 9 words and
    // spreads by shifts d=1,2,4 with cross-word carries -> radius 7.
    if (tid < IN_ROWS * 2) {
        const int  ir    = tid >> 1;
        const bool doOne = (tid & 1) != 0;
        uint32_t m[IN_WORDS];
        #pragma unroll
        for (int i = 0; i < IN_WORDS; i++)
            m[i] = doOne ? sB1[ir][i] : sM0[ir][i];

        #pragma unroll
        for (int s = 0; s < 3; s++) {
            const int d = 1 << s;          // 1, 2, 4  -> cumulative radius 1,3,7
            uint32_t t2[IN_WORDS];
            #pragma unroll
            for (int i = 0; i < IN_WORDS; i++) {
                uint32_t lo = (i > 0)            ? m[i - 1] : 0u;
                uint32_t hi = (i < IN_WORDS - 1) ? m[i + 1] : 0u;
                t2[i] = m[i]
                      | (m[i] << d) | (lo >> (32 - d))
                      | (m[i] >> d) | (hi << (32 - d));
            }
            #pragma unroll
            for (int i = 0; i < IN_WORDS; i++) m[i] = t2[i];
        }

        if (doOne) {
            #pragma unroll
            for (int i = 0; i < IN_WORDS; i++) sH1[ir][i] = m[i];
        } else {
            #pragma unroll
            for (int i = 0; i < IN_WORDS; i++) sM0[ir][i] = m[i];
        }
    }
    __syncthreads();

    // ---------------- Phase 3: vertical OR (fused) + gather + reduce --------
    float    fsum = 0.0f;
    unsigned fcnt = 0u;

    for (int r = warp; r < TY; r += NWARPS) {
        const int y = y0 + r;
        if (y >= HH) break;
        #pragma unroll
        for (int wi = 0; wi < IN_WORDS; wi++) {
            // Vertical 15-row OR via lane-parallel reduce (rows r..r+14).
            // Stride 9 words/row is coprime with 32 banks -> conflict-free.
            const uint32_t a1 = (lane < 15) ? sH1[r + lane][wi] : 0u;
            const uint32_t v1 = __reduce_or_sync(0xffffffffu, a1);
            const uint32_t a0 = (lane < 15) ? sM0[r + lane][wi] : 0u;
            const uint32_t v0 = __reduce_or_sync(0xffffffffu, a0);
            const uint32_t valid = v0 & v1;   // window has both classes
            if (!valid) continue;

            const int col = baseCol + (wi << 5) + lane;
            const bool ok = ((valid >> lane) & 1u) &&
                            col >= x0 && col < x0 + TX && col < WW;
            if (ok) {
                // center pixel's label: its own bit in the preserved b1 mask
                const int lbl = (sB1[r + RADIUS][wi] >> lane) & 1;
                const float lp = logits[((b * CH + lbl) * HH + y) * WW + col];
                fsum += lp;
                fcnt += 1u;
            }
        }
    }

    // warp reduce
    #pragma unroll
    for (int o = 16; o > 0; o >>= 1) {
        fsum += __shfl_down_sync(0xffffffffu, fsum, o);
        fcnt += __shfl_down_sync(0xffffffffu, fcnt, o);
    }
    if (lane == 0) { sPartS[warp] = fsum; sPartC[warp] = fcnt; }
    __syncthreads();

    if (tid == 0) {
        double s = 0.0;
        unsigned long long c = 0ULL;
        #pragma unroll
        for (int i = 0; i < NWARPS; i++) { s += (double)sPartS[i]; c += sPartC[i]; }
        atomicAdd(&g_sum, s);
        atomicAdd(&g_cnt, c);
    }
}

__global__ void bl_finalize_kernel(float* __restrict__ out) {
    unsigned long long c = g_cnt;
    if (c == 0ULL) c = 1ULL;
    out[0] = (float)(-g_sum / (double)c);
}

extern "C" void kernel_launch(void* const* d_in, const int* in_sizes, int n_in,
                              void* d_out, int out_size) {
    const float* logits = (const float*)d_in[0];
    const int*   labels = (const int*)d_in[1];
    float*       out    = (float*)d_out;

    bl_init_kernel<<<1, 1>>>();

    dim3 grid((WW + TX - 1) / TX,   // 4
              (HH + TY - 1) / TY,   // 8
              BATCH);               // 32  -> 1024 blocks
    boundary_loss_kernel<<<grid, NTHREADS>>>(logits, labels);

    bl_finalize_kernel<<<1, 1>>>(out);
}